// round 12
// baseline (speedup 1.0000x reference)
#include <cuda_runtime.h>
#include <cuda_fp16.h>
#include <stdint.h>

// ============================================================================
// EnhancedAntiOverfittingAugmentation — round 12: pair-packed 16B staging.
//  - staging entry E[y][x] = {pix[x], pix[x+1]}, pix = {h2(R,G), h2(B,0)}
//    -> bilinear row tap = ONE LDS.128 (both x-taps, all 3 channels)
//    -> gather: 2 LDS/px (was 4), one shared address calc
//  - all arithmetic fp32 (fp16 storage only; rel_err ~1.2e-4)
//  - register-resident warped image (4 px x 3 ch per thread @ NT=1024)
//  - non-blur CTAs: regs -> jitter/masks -> out; blur CTAs: fp32 SMEM overlay
//  - uniform table-driven Threefry param generation (warp 0)
// Randomness replicates JAX Threefry-2x32, threefry_partitionable=True.
// 1024 thr, 74KB smem, 2 CTAs/SM.
// ============================================================================

#define NT 1024
#define BATCH 2048
#define HWpx 4096
#define CHW 12288
#define ESTRIDE 68                // 16B entries per staging row
#define SMEM_BYTES (68 * 68 * 16) // 73984 B (> blur overlay 53856 B)
// blur overlay planes (1px pad), fp32, overlaid on dead staging
#define WSTR 68
#define WPLANE (66 * 68)          // 4488 floats

__constant__ int   c_parent[16] = {0,0,0,0, 2,2,2, 4,4,4,4,4,4, 5,5, 0};
__constant__ int   c_child[16]  = {0,1,2,3, 0,1,2, 0,1,2,3,4,5, 0,1, 0};
__constant__ int   c_src[17]    = {6,7,8,9,9, 1, 10,11,12, 3, 13,14,15,16, 18, 19, 20};
__constant__ int   c_cnt[17]    = {0,0,0,1,2, 0, 0,0,0, 0, 0,0,0,0, 0, 0, 0};
__constant__ float c_lo[17]  = {-25.f,-15.f,0.85f,-0.15f,-0.15f, 0.f, 0.7f,0.7f,0.8f,
                                0.f, 0.02f,0.3f,0.f,0.f, 0.f, 8.f, 0.f};
__constant__ float c_hi[17]  = {25.f,15.f,1.15f,0.15f,0.15f, 1.f, 1.3f,1.3f,1.2f,
                                1.f, 0.1f,3.0f,1.f,1.f, 1.f, 32.f, 1.f};
#define DEGf 0.017453292519943295f
__constant__ float c_mul[17] = {DEGf,DEGf,1.f,1.f,1.f, 1.f, 1.f,1.f,1.f,
                                1.f, 1.f,1.f,1.f,1.f, 1.f, 1.f, 1.f};

__device__ __forceinline__ uint32_t rotl32(uint32_t v, int d) {
    return (v << d) | (v >> (32 - d));
}

// Threefry-2x32, 20 rounds, exactly as in jax._src.prng
__device__ __forceinline__ void tf2x32(uint32_t k0, uint32_t k1,
                                       uint32_t x0, uint32_t x1,
                                       uint32_t &o0, uint32_t &o1) {
    const uint32_t ks2 = k0 ^ k1 ^ 0x1BD11BDAu;
    x0 += k0; x1 += k1;
#define TFR(r) { x0 += x1; x1 = rotl32(x1, (r)); x1 ^= x0; }
    TFR(13) TFR(15) TFR(26) TFR(6)   x0 += k1;  x1 += ks2 + 1u;
    TFR(17) TFR(29) TFR(16) TFR(24)  x0 += ks2; x1 += k0 + 2u;
    TFR(13) TFR(15) TFR(26) TFR(6)   x0 += k0;  x1 += k1 + 3u;
    TFR(17) TFR(29) TFR(16) TFR(24)  x0 += k1;  x1 += ks2 + 4u;
    TFR(13) TFR(15) TFR(26) TFR(6)   x0 += ks2; x1 += k0 + 5u;
#undef TFR
    o0 = x0; o1 = x1;
}

__device__ __forceinline__ uint32_t rb32(uint32_t k0, uint32_t k1, uint32_t idx) {
    uint32_t a, b; tf2x32(k0, k1, 0u, idx, a, b); return a ^ b;
}

__device__ __forceinline__ float u01f(uint32_t bits) {
    return __uint_as_float((bits >> 9) | 0x3f800000u) - 1.0f;
}
__device__ __forceinline__ float unif(uint32_t bits, float lo, float hi) {
    return fmaxf(lo, u01f(bits) * (hi - lo) + lo);
}

__device__ __forceinline__ uint32_t packh2(float a, float b) {
    __half2 h = __floats2half2_rn(a, b);
    return *reinterpret_cast<uint32_t*>(&h);
}

struct SampleParams {
    float m00, m01, m10, m11, tx, ty;
    float br, ct, st;
    uint32_t kv0, kv1;
    int flip, blur, eapply, gapply;
};

__global__ void __launch_bounds__(NT, 2)
aug_kernel(const float* __restrict__ gin, float* __restrict__ gout) {
    extern __shared__ float smem[];
    uint4* sE = (uint4*)smem;      // pair-packed staging entries
    __shared__ SampleParams P;
    __shared__ float red[NT / 32];
    __shared__ uint32_t K[42];
    __shared__ float U[17];
    __shared__ uint32_t gm[2], er_row[2], er_col[2];

    const int b = blockIdx.x;
    const int tid = threadIdx.x;

    // ================= params, uniform control flow (warp 0) =================
    if (tid < 32) {
        const int lane = tid;
        const uint32_t ub = (uint32_t)b;
        uint32_t o0, o1;
        tf2x32(0u, 42u, 0u, (uint32_t)min(lane, 5), o0, o1);
        if (lane < 6) { K[2 * lane] = o0; K[2 * lane + 1] = o1; }
        __syncwarp();
        {
            int li = min(lane, 15);
            int p = c_parent[li];
            tf2x32(K[2 * p], K[2 * p + 1], 0u, (uint32_t)c_child[li], o0, o1);
            if (lane < 15) { K[12 + 2 * lane] = o0; K[13 + 2 * lane] = o1; }
        }
        __syncwarp();
        {
            int li = min(lane, 16);
            int s = c_src[li];
            int cs = c_cnt[li];
            uint32_t cnt = (cs == 0) ? ub : ((cs == 1) ? 2u * ub : 2u * ub + 1u);
            uint32_t bits = rb32(K[2 * s], K[2 * s + 1], cnt);
            float u = unif(bits, c_lo[li], c_hi[li]) * c_mul[li];
            if (lane == 15) u = floorf(u);
            if (lane < 17) U[lane] = u;
        }
        __syncwarp();
        {
            float ang = U[0], shr = U[1], scl = U[2];
            float cc = cosf(ang), ss = sinf(ang), t = tanf(shr);
            float m00 = (cc - t * (-ss)) / scl;
            float m01 = (ss - t * cc) / scl;
            float m10 = (-ss) / scl;
            float m11 = cc / scl;
            float area = (U[10] * 64.0f) * 64.0f;
            float ratio = U[11];
            float eh = fminf(fmaxf(sqrtf(area * ratio), 1.0f), 64.0f);
            float ew = fminf(fmaxf(sqrtf(area / ratio), 1.0f), 64.0f);
            float top = U[12] * (64.0f - eh);
            float left = U[13] * (64.0f - ew);
            if (lane == 0) {
                P.m00 = m00; P.m01 = m01; P.m10 = m10; P.m11 = m11;
                P.tx = U[3] * 64.0f;  P.ty = U[4] * 64.0f;
                P.flip = (U[5] < 0.6f);
                P.br = U[6]; P.ct = U[7]; P.st = U[8];
                P.blur = (U[9] < 0.3f);
                P.eapply = (U[14] < 0.3f);
                P.gapply = (U[16] < 0.3f);
                P.kv0 = K[34]; P.kv1 = K[35];
            }
            __syncwarp();
            float c0 = (float)lane, c1 = (float)(lane + 32);
            float gd = U[15], gl = floorf(U[15] * 0.6f);
            uint32_t g0 = __ballot_sync(0xffffffffu, fmodf(c0, gd) < gl);
            uint32_t g1 = __ballot_sync(0xffffffffu, fmodf(c1, gd) < gl);
            uint32_t r0 = __ballot_sync(0xffffffffu, c0 >= top && c0 < top + eh);
            uint32_t r1 = __ballot_sync(0xffffffffu, c1 >= top && c1 < top + eh);
            uint32_t q0 = __ballot_sync(0xffffffffu, c0 >= left && c0 < left + ew);
            uint32_t q1 = __ballot_sync(0xffffffffu, c1 >= left && c1 < left + ew);
            if (lane == 0) {
                gm[0] = g0; gm[1] = g1;
                er_row[0] = r0; er_row[1] = r1;
                er_col[0] = q0; er_col[1] = q1;
            }
        }
    }

    // ================= staging border zero (464 x 16B entries) ===============
    // full rows {0,1,66,67}: 68 entries each (272); cols {0,66,67} rows 2..65 (192)
    if (tid < 464) {
        int eidx;
        if (tid < 272) {
            int r = tid / 68, col = tid % 68;
            int row = (r < 2) ? r : 64 + r;
            eidx = row * ESTRIDE + col;
        } else {
            int j = tid - 272;
            int row = 2 + j / 3;
            int sel = j % 3;
            int col = (sel == 0) ? 0 : (65 + sel);   // 0, 66, 67
            eidx = row * ESTRIDE + col;
        }
        sE[eidx] = make_uint4(0u, 0u, 0u, 0u);
    }

    // ================= interior load: planar global -> pair entries ==========
    {
        const float4* gin4 = (const float4*)(gin + (size_t)b * CHW);
        int q = tid;                           // one quad (4px) per thread
        float4 R4 = gin4[q];
        float4 G4 = gin4[q + 1024];
        float4 B4 = gin4[q + 2048];
        // neighbor quad's first pixel (same row) via shfl; lanes with
        // (q&15)==15 are row-end -> border zero (shfl result unused there)
        float Rn = __shfl_down_sync(0xffffffffu, R4.x, 1);
        float Gn = __shfl_down_sync(0xffffffffu, G4.x, 1);
        float Bn = __shfl_down_sync(0xffffffffu, B4.x, 1);
        if ((q & 15) == 15) { Rn = 0.f; Gn = 0.f; Bn = 0.f; }
        int h = q >> 4, w = (q & 15) << 2;
        uint32_t rg0 = packh2(R4.x, G4.x), b0 = packh2(B4.x, 0.f);
        uint32_t rg1 = packh2(R4.y, G4.y), b1 = packh2(B4.y, 0.f);
        uint32_t rg2 = packh2(R4.z, G4.z), b2 = packh2(B4.z, 0.f);
        uint32_t rg3 = packh2(R4.w, G4.w), b3 = packh2(B4.w, 0.f);
        uint32_t rg4 = packh2(Rn, Gn),     b4 = packh2(Bn, 0.f);
        uint4* E = sE + (h + 2) * ESTRIDE + (w + 2);
        E[0] = make_uint4(rg0, b0, rg1, b1);
        E[1] = make_uint4(rg1, b1, rg2, b2);
        E[2] = make_uint4(rg2, b2, rg3, b3);
        E[3] = make_uint4(rg3, b3, rg4, b4);
        if (w == 0)   // entry covering (border px, first image px)
            sE[(h + 2) * ESTRIDE + 1] = make_uint4(0u, 0u, rg0, b0);
    }
    __syncthreads();

    // ================= phase 1: gather into registers + sum ==================
    const float m00 = P.m00, m01 = P.m01, m10 = P.m10, m11 = P.m11;
    const bool flip = P.flip;
    const bool doblur = P.blur;
    const int w = tid & 63;
    const int h0 = tid >> 6;         // 0..15; rows h0 + 16k
    const int wd = flip ? (63 - w) : w;

    float vr[4], vg[4], vb[4];
    {
        const float gx = (float)w - 31.5f;
        float sx = m00 * gx + m01 * ((float)h0 - 31.5f) - P.tx + 31.5f;
        float sy = m10 * gx + m11 * ((float)h0 - 31.5f) - P.ty + 31.5f;
        const float dx16 = 16.0f * m01, dy16 = 16.0f * m11;
        float lsum = 0.f;
        #pragma unroll
        for (int k = 0; k < 4; k++) {
            float x0f = floorf(sx), y0f = floorf(sy);
            float wx = sx - x0f, wy = sy - y0f;
            int xi = min(max((int)x0f, -2), 64);
            int yi = min(max((int)y0f, -2), 64);
            const int eidx = (yi + 2) * ESTRIDE + (xi + 2);
            uint4 T = sE[eidx];              // top row: both x-taps, 3 ch
            uint4 Bo = sE[eidx + ESTRIDE];   // bottom row
            float2 p00 = __half22float2(*(const __half2*)&T.x);
            float  b00 = __half2float(*(const __half*)&T.y);
            float2 p01 = __half22float2(*(const __half2*)&T.z);
            float  b01 = __half2float(*(const __half*)&T.w);
            float2 p10 = __half22float2(*(const __half2*)&Bo.x);
            float  b10 = __half2float(*(const __half*)&Bo.y);
            float2 p11 = __half22float2(*(const __half2*)&Bo.z);
            float  b11 = __half2float(*(const __half*)&Bo.w);
            float w11 = wx * wy;
            float w01 = wx - w11;
            float w10 = wy - w11;
            float w00 = 1.0f - wx - wy + w11;
            vr[k] = p00.x * w00 + p01.x * w01 + p10.x * w10 + p11.x * w11;
            vg[k] = p00.y * w00 + p01.y * w01 + p10.y * w10 + p11.y * w11;
            vb[k] = b00  * w00 + b01  * w01 + b10  * w10 + b11  * w11;
            lsum += vr[k] + vg[k] + vb[k];
            sx += dx16; sy += dy16;
        }
        #pragma unroll
        for (int off = 16; off > 0; off >>= 1)
            lsum += __shfl_xor_sync(0xffffffffu, lsum, off);
        if ((tid & 31) == 0) red[tid >> 5] = lsum;
    }
    __syncthreads();   // red ready; staging now DEAD (all gathers done)

    // ---------------- per-warp mean finish (32 partials) ----------------
    float alpha, beta, delta;
    {
        const int lane = tid & 31;
        float t = red[lane];
        #pragma unroll
        for (int off = 16; off > 0; off >>= 1)
            t += __shfl_xor_sync(0xffffffffu, t, off);
        float mean = (P.br * t) * (1.0f / 12288.0f);
        float bc = P.br * P.ct;
        alpha = P.st * bc;
        beta  = (1.0f - P.st) * bc;
        delta = mean * (1.0f - P.ct);
    }
    const bool eap = P.eapply, gap = P.gapply;
    const uint32_t kv0 = P.kv0, kv1 = P.kv1;
    float* o = gout + (size_t)b * CHW;
    const bool ecol_hit = eap && ((er_col[wd >> 5] >> (wd & 31)) & 1u);
    const bool gcol_hit = gap && ((gm[wd >> 5] >> (wd & 31)) & 1u);

    if (!doblur) {
        // ========== non-blur: jitter + masks + clamp straight from regs ======
        #pragma unroll
        for (int k = 0; k < 4; k++) {
            const int h = h0 + 16 * k;
            float r = vr[k], g = vg[k], bl = vb[k];
            float gray = 0.299f * r + 0.587f * g + 0.114f * bl;
            float v0 = alpha * r  + beta * gray + delta;
            float v1 = alpha * g  + beta * gray + delta;
            float v2 = alpha * bl + beta * gray + delta;
            if (ecol_hit && ((er_row[h >> 5] >> (h & 31)) & 1u)) {
                uint32_t rbase = ((uint32_t)b * 3u) * 4096u + (uint32_t)(h * 64 + wd);
                v0 = u01f(rb32(kv0, kv1, rbase));
                v1 = u01f(rb32(kv0, kv1, rbase + 4096u));
                v2 = u01f(rb32(kv0, kv1, rbase + 8192u));
            }
            if (gcol_hit && ((gm[h >> 5] >> (h & 31)) & 1u)) {
                v0 = 0.f; v1 = 0.f; v2 = 0.f;
            }
            const int base = h * 64 + wd;
            o[base]            = fminf(fmaxf(v0, 0.f), 1.f);
            o[HWpx + base]     = fminf(fmaxf(v1, 0.f), 1.f);
            o[2 * HWpx + base] = fminf(fmaxf(v2, 0.f), 1.f);
        }
    } else {
        // ========== blur: spill regs -> fp32 padded overlay, 9-tap, jitter ===
        if (tid < 792) {
            int i = tid;
            int plane = i / 264;
            int r = i - plane * 264;
            int row, col;
            if (r < 136) { row = (r < 68) ? 0 : 65; col = (r < 68) ? r : r - 68; }
            else { int r2 = r - 136; row = 1 + (r2 >> 1); col = (r2 & 1) ? 65 : 0; }
            smem[plane * WPLANE + row * WSTR + col] = 0.f;
        }
        #pragma unroll
        for (int k = 0; k < 4; k++) {
            const int h = h0 + 16 * k;
            const int off = (h + 1) * WSTR + (wd + 1);
            smem[off]              = vr[k];
            smem[WPLANE + off]     = vg[k];
            smem[2 * WPLANE + off] = vb[k];
        }
        __syncthreads();

        const float rx = 1.0f - 0.25f * ((wd == 0) + (wd == 63));
        #pragma unroll
        for (int k = 0; k < 4; k++) {
            const int h = h0 + 16 * k;
            float v[3];
            #pragma unroll
            for (int c = 0; c < 3; c++) {
                const float* p = smem + c * WPLANE + h * WSTR + wd;  // window TL
                float t0 = 0.25f * (p[0] + p[2]) + 0.5f * p[1];
                float t1 = 0.25f * (p[WSTR] + p[WSTR + 2]) + 0.5f * p[WSTR + 1];
                float t2 = 0.25f * (p[2 * WSTR] + p[2 * WSTR + 2]) + 0.5f * p[2 * WSTR + 1];
                v[c] = 0.25f * (t0 + t2) + 0.5f * t1;
            }
            float S = rx * (1.0f - 0.25f * ((h == 0) + (h == 63)));
            float gray = 0.299f * v[0] + 0.587f * v[1] + 0.114f * v[2];
            float dd = delta * S;
            float v0 = alpha * v[0] + beta * gray + dd;
            float v1 = alpha * v[1] + beta * gray + dd;
            float v2 = alpha * v[2] + beta * gray + dd;
            if (ecol_hit && ((er_row[h >> 5] >> (h & 31)) & 1u)) {
                uint32_t rbase = ((uint32_t)b * 3u) * 4096u + (uint32_t)(h * 64 + wd);
                v0 = u01f(rb32(kv0, kv1, rbase));
                v1 = u01f(rb32(kv0, kv1, rbase + 4096u));
                v2 = u01f(rb32(kv0, kv1, rbase + 8192u));
            }
            if (gcol_hit && ((gm[h >> 5] >> (h & 31)) & 1u)) {
                v0 = 0.f; v1 = 0.f; v2 = 0.f;
            }
            const int base = h * 64 + wd;
            o[base]            = fminf(fmaxf(v0, 0.f), 1.f);
            o[HWpx + base]     = fminf(fmaxf(v1, 0.f), 1.f);
            o[2 * HWpx + base] = fminf(fmaxf(v2, 0.f), 1.f);
        }
    }
}

extern "C" void kernel_launch(void* const* d_in, const int* in_sizes, int n_in,
                              void* d_out, int out_size) {
    (void)in_sizes; (void)n_in; (void)out_size;
    const float* x = (const float*)d_in[0];
    float* out = (float*)d_out;
    cudaFuncSetAttribute(aug_kernel, cudaFuncAttributeMaxDynamicSharedMemorySize,
                         SMEM_BYTES);
    aug_kernel<<<BATCH, NT, SMEM_BYTES>>>(x, out);
}

// round 13
// speedup vs baseline: 1.0188x; 1.0188x over previous
#include <cuda_runtime.h>
#include <cuda_fp16.h>
#include <stdint.h>

// ============================================================================
// EnhancedAntiOverfittingAugmentation — round 13: R11 staging + STG.128
// outputs (row-quad thread mapping) + compile-time Threefry key table.
//  - staging: {h2(R,G), h2(B,0)} 8B/px, 68x68, 2px border (R11, best-known)
//  - thread owns 4 consecutive output px (h, 4q..4q+3) -> 3x STG.128
//  - keys constexpr-folded into __constant__; warp 0 only does the 17 uniforms
//  - register-resident warped image; blur via fp32 SMEM overlay
// Randomness replicates JAX Threefry-2x32, threefry_partitionable=True.
// 1024 thr, 53.9KB smem, 2 CTAs/SM.
// ============================================================================

#define NT 1024
#define BATCH 2048
#define HWpx 4096
#define CHW 12288
#define ESTRIDE 68                // 8B entries per staging row
// blur overlay planes (1px pad), fp32, overlaid on dead staging
#define WSTR 68
#define WPLANE (66 * 68)          // 4488 floats
#define SMEM_BYTES (3 * WPLANE * 4)   // 53856 B (> staging 36992 B)

// ---------------- compile-time Threefry key table ----------------
struct TFPair { uint32_t a, b; };
constexpr uint32_t crotl(uint32_t v, int d) { return (v << d) | (v >> (32 - d)); }
constexpr TFPair ctf(uint32_t k0, uint32_t k1, uint32_t x0, uint32_t x1) {
    uint32_t ks2 = k0 ^ k1 ^ 0x1BD11BDAu;
    x0 += k0; x1 += k1;
#define CTFR(r) { x0 += x1; x1 = crotl(x1, (r)); x1 ^= x0; }
    CTFR(13) CTFR(15) CTFR(26) CTFR(6)   x0 += k1;  x1 += ks2 + 1u;
    CTFR(17) CTFR(29) CTFR(16) CTFR(24)  x0 += ks2; x1 += k0 + 2u;
    CTFR(13) CTFR(15) CTFR(26) CTFR(6)   x0 += k0;  x1 += k1 + 3u;
    CTFR(17) CTFR(29) CTFR(16) CTFR(24)  x0 += k1;  x1 += ks2 + 4u;
    CTFR(13) CTFR(15) CTFR(26) CTFR(6)   x0 += ks2; x1 += k0 + 5u;
#undef CTFR
    return {x0, x1};
}
struct KTab { uint32_t v[42]; };
constexpr KTab make_keys() {
    KTab t{};
    const int par[15] = {0,0,0,0, 2,2,2, 4,4,4,4,4,4, 5,5};
    const int chi[15] = {0,1,2,3, 0,1,2, 0,1,2,3,4,5, 0,1};
    for (int i = 0; i < 6; i++) {
        TFPair p = ctf(0u, 42u, 0u, (uint32_t)i);
        t.v[2 * i] = p.a; t.v[2 * i + 1] = p.b;
    }
    for (int i = 0; i < 15; i++) {
        int pa = par[i];
        TFPair p = ctf(t.v[2 * pa], t.v[2 * pa + 1], 0u, (uint32_t)chi[i]);
        t.v[12 + 2 * i] = p.a; t.v[13 + 2 * i] = p.b;
    }
    return t;
}
__constant__ KTab cK = make_keys();

__constant__ int   c_src[17] = {6,7,8,9,9, 1, 10,11,12, 3, 13,14,15,16, 18, 19, 20};
__constant__ int   c_cnt[17] = {0,0,0,1,2, 0, 0,0,0, 0, 0,0,0,0, 0, 0, 0};
__constant__ float c_lo[17]  = {-25.f,-15.f,0.85f,-0.15f,-0.15f, 0.f, 0.7f,0.7f,0.8f,
                                0.f, 0.02f,0.3f,0.f,0.f, 0.f, 8.f, 0.f};
__constant__ float c_hi[17]  = {25.f,15.f,1.15f,0.15f,0.15f, 1.f, 1.3f,1.3f,1.2f,
                                1.f, 0.1f,3.0f,1.f,1.f, 1.f, 32.f, 1.f};
#define DEGf 0.017453292519943295f
__constant__ float c_mul[17] = {DEGf,DEGf,1.f,1.f,1.f, 1.f, 1.f,1.f,1.f,
                                1.f, 1.f,1.f,1.f,1.f, 1.f, 1.f, 1.f};

__device__ __forceinline__ uint32_t rotl32(uint32_t v, int d) {
    return (v << d) | (v >> (32 - d));
}

// Threefry-2x32, 20 rounds (device runtime version)
__device__ __forceinline__ void tf2x32(uint32_t k0, uint32_t k1,
                                       uint32_t x0, uint32_t x1,
                                       uint32_t &o0, uint32_t &o1) {
    const uint32_t ks2 = k0 ^ k1 ^ 0x1BD11BDAu;
    x0 += k0; x1 += k1;
#define TFR(r) { x0 += x1; x1 = rotl32(x1, (r)); x1 ^= x0; }
    TFR(13) TFR(15) TFR(26) TFR(6)   x0 += k1;  x1 += ks2 + 1u;
    TFR(17) TFR(29) TFR(16) TFR(24)  x0 += ks2; x1 += k0 + 2u;
    TFR(13) TFR(15) TFR(26) TFR(6)   x0 += k0;  x1 += k1 + 3u;
    TFR(17) TFR(29) TFR(16) TFR(24)  x0 += k1;  x1 += ks2 + 4u;
    TFR(13) TFR(15) TFR(26) TFR(6)   x0 += ks2; x1 += k0 + 5u;
#undef TFR
    o0 = x0; o1 = x1;
}

__device__ __forceinline__ uint32_t rb32(uint32_t k0, uint32_t k1, uint32_t idx) {
    uint32_t a, b; tf2x32(k0, k1, 0u, idx, a, b); return a ^ b;
}

__device__ __forceinline__ float u01f(uint32_t bits) {
    return __uint_as_float((bits >> 9) | 0x3f800000u) - 1.0f;
}
__device__ __forceinline__ float unif(uint32_t bits, float lo, float hi) {
    return fmaxf(lo, u01f(bits) * (hi - lo) + lo);
}

__device__ __forceinline__ uint32_t h2u(__half2 h) {
    return *reinterpret_cast<uint32_t*>(&h);
}

struct SampleParams {
    float m00, m01, m10, m11, tx, ty;
    float br, ct, st;
    int flip, blur, eapply, gapply;
};

__global__ void __launch_bounds__(NT, 2)
aug_kernel(const float* __restrict__ gin, float* __restrict__ gout) {
    extern __shared__ float smem[];
    uint2* sPix = (uint2*)smem;    // staging: {h2(R,G), h2(B,0)} per px
    __shared__ SampleParams P;
    __shared__ float red[NT / 32];
    __shared__ float U[17];
    __shared__ uint32_t gm[2], er_row[2], er_col[2];

    const int b = blockIdx.x;
    const int tid = threadIdx.x;

    // ================= params (warp 0): 17 uniforms from constexpr keys ======
    if (tid < 32) {
        const int lane = tid;
        const uint32_t ub = (uint32_t)b;
        {
            int li = min(lane, 16);
            int s = c_src[li];
            int cs = c_cnt[li];
            uint32_t cnt = (cs == 0) ? ub : ((cs == 1) ? 2u * ub : 2u * ub + 1u);
            uint32_t bits = rb32(cK.v[2 * s], cK.v[2 * s + 1], cnt);
            float u = unif(bits, c_lo[li], c_hi[li]) * c_mul[li];
            if (lane == 15) u = floorf(u);
            if (lane < 17) U[lane] = u;
        }
        __syncwarp();
        {
            float ang = U[0], shr = U[1], scl = U[2];
            float cc = cosf(ang), ss = sinf(ang), t = tanf(shr);
            float m00 = (cc - t * (-ss)) / scl;
            float m01 = (ss - t * cc) / scl;
            float m10 = (-ss) / scl;
            float m11 = cc / scl;
            float area = (U[10] * 64.0f) * 64.0f;
            float ratio = U[11];
            float eh = fminf(fmaxf(sqrtf(area * ratio), 1.0f), 64.0f);
            float ew = fminf(fmaxf(sqrtf(area / ratio), 1.0f), 64.0f);
            float top = U[12] * (64.0f - eh);
            float left = U[13] * (64.0f - ew);
            if (lane == 0) {
                P.m00 = m00; P.m01 = m01; P.m10 = m10; P.m11 = m11;
                P.tx = U[3] * 64.0f;  P.ty = U[4] * 64.0f;
                P.flip = (U[5] < 0.6f);
                P.br = U[6]; P.ct = U[7]; P.st = U[8];
                P.blur = (U[9] < 0.3f);
                P.eapply = (U[14] < 0.3f);
                P.gapply = (U[16] < 0.3f);
            }
            __syncwarp();
            float c0 = (float)lane, c1 = (float)(lane + 32);
            float gd = U[15], gl = floorf(U[15] * 0.6f);
            uint32_t g0 = __ballot_sync(0xffffffffu, fmodf(c0, gd) < gl);
            uint32_t g1 = __ballot_sync(0xffffffffu, fmodf(c1, gd) < gl);
            uint32_t r0 = __ballot_sync(0xffffffffu, c0 >= top && c0 < top + eh);
            uint32_t r1 = __ballot_sync(0xffffffffu, c1 >= top && c1 < top + eh);
            uint32_t q0 = __ballot_sync(0xffffffffu, c0 >= left && c0 < left + ew);
            uint32_t q1 = __ballot_sync(0xffffffffu, c1 >= left && c1 < left + ew);
            if (lane == 0) {
                gm[0] = g0; gm[1] = g1;
                er_row[0] = r0; er_row[1] = r1;
                er_col[0] = q0; er_col[1] = q1;
            }
        }
    }

    // ================= staging border zero (264 uint4 = 16B each) ============
    if (tid < 264) {
        int i = tid;
        int eidx;                       // entry index (8B units), even
        if (i < 136) {
            int r = i / 34, c2 = i % 34;
            int row = (r < 2) ? r : 64 + r;
            eidx = row * ESTRIDE + c2 * 2;
        } else {
            int j = i - 136;
            int r = 2 + (j >> 1);
            eidx = r * ESTRIDE + ((j & 1) ? 66 : 0);
        }
        *(uint4*)(sPix + eidx) = make_uint4(0u, 0u, 0u, 0u);
    }

    // ================= interior load: planar global -> packed entries ========
    {
        const float4* gin4 = (const float4*)(gin + (size_t)b * CHW);
        int q = tid;                           // one quad (4px) per thread
        float4 R4 = gin4[q];
        float4 G4 = gin4[q + 1024];
        float4 B4 = gin4[q + 2048];
        int h = q >> 4, w = (q & 15) << 2;
        int ebase = (h + 2) * ESTRIDE + (w + 2);   // even -> 16B aligned
        uint4 u0 = make_uint4(
            h2u(__floats2half2_rn(R4.x, G4.x)), h2u(__floats2half2_rn(B4.x, 0.f)),
            h2u(__floats2half2_rn(R4.y, G4.y)), h2u(__floats2half2_rn(B4.y, 0.f)));
        uint4 u1 = make_uint4(
            h2u(__floats2half2_rn(R4.z, G4.z)), h2u(__floats2half2_rn(B4.z, 0.f)),
            h2u(__floats2half2_rn(R4.w, G4.w)), h2u(__floats2half2_rn(B4.w, 0.f)));
        *(uint4*)(sPix + ebase)     = u0;
        *(uint4*)(sPix + ebase + 2) = u1;
    }
    __syncthreads();

    // ================= phase 1: gather 4 consecutive output px ===============
    const float m00 = P.m00, m01 = P.m01, m10 = P.m10, m11 = P.m11;
    const bool flip = P.flip;
    const bool doblur = P.blur;
    const int h = tid >> 4;          // output row 0..63
    const int wb = (tid & 15) << 2;  // output col base (16B aligned)

    float vr[4], vg[4], vb[4];
    {
        const float gy = (float)h - 31.5f;
        const int wc0 = flip ? (63 - wb) : wb;     // source col of output wb
        float sx = m00 * ((float)wc0 - 31.5f) + m01 * gy - P.tx + 31.5f;
        float sy = m10 * ((float)wc0 - 31.5f) + m11 * gy - P.ty + 31.5f;
        const float dsx = flip ? -m00 : m00;
        const float dsy = flip ? -m10 : m10;
        float lsum = 0.f;
        #pragma unroll
        for (int k = 0; k < 4; k++) {
            float x0f = floorf(sx), y0f = floorf(sy);
            float wx = sx - x0f, wy = sy - y0f;
            int xi = min(max((int)x0f, -2), 64);
            int yi = min(max((int)y0f, -2), 64);
            const int eidx = (yi + 2) * ESTRIDE + (xi + 2);
            uint2 e00 = sPix[eidx];
            uint2 e01 = sPix[eidx + 1];
            uint2 e10 = sPix[eidx + ESTRIDE];
            uint2 e11 = sPix[eidx + ESTRIDE + 1];
            float2 p00 = __half22float2(*(const __half2*)&e00.x);
            float2 p01 = __half22float2(*(const __half2*)&e01.x);
            float2 p10 = __half22float2(*(const __half2*)&e10.x);
            float2 p11 = __half22float2(*(const __half2*)&e11.x);
            float b00 = __half2float(*(const __half*)&e00.y);
            float b01 = __half2float(*(const __half*)&e01.y);
            float b10 = __half2float(*(const __half*)&e10.y);
            float b11 = __half2float(*(const __half*)&e11.y);
            float w11 = wx * wy;
            float w01 = wx - w11;
            float w10 = wy - w11;
            float w00 = 1.0f - wx - wy + w11;
            vr[k] = p00.x * w00 + p01.x * w01 + p10.x * w10 + p11.x * w11;
            vg[k] = p00.y * w00 + p01.y * w01 + p10.y * w10 + p11.y * w11;
            vb[k] = b00  * w00 + b01  * w01 + b10  * w10 + b11  * w11;
            lsum += vr[k] + vg[k] + vb[k];
            sx += dsx; sy += dsy;
        }
        #pragma unroll
        for (int off = 16; off > 0; off >>= 1)
            lsum += __shfl_xor_sync(0xffffffffu, lsum, off);
        if ((tid & 31) == 0) red[tid >> 5] = lsum;
    }
    __syncthreads();   // red ready; staging now DEAD

    // ---------------- per-warp mean finish (32 partials) ----------------
    float alpha, beta, delta;
    {
        const int lane = tid & 31;
        float t = red[lane];
        #pragma unroll
        for (int off = 16; off > 0; off >>= 1)
            t += __shfl_xor_sync(0xffffffffu, t, off);
        float mean = (P.br * t) * (1.0f / 12288.0f);
        float bc = P.br * P.ct;
        alpha = P.st * bc;
        beta  = (1.0f - P.st) * bc;
        delta = mean * (1.0f - P.ct);
    }
    const bool eap = P.eapply, gap = P.gapply;
    const uint32_t kv0 = cK.v[34], kv1 = cK.v[35];
    float* o = gout + (size_t)b * CHW;
    const int base = h * 64 + wb;
    const bool ghit_h = gap && ((gm[h >> 5] >> (h & 31)) & 1u);
    const bool ehit_h = eap && ((er_row[h >> 5] >> (h & 31)) & 1u);

    if (doblur) {
        // spill regs -> fp32 padded overlay; 6-wide window reuse per thread
        if (tid < 792) {
            int i = tid;
            int plane = i / 264;
            int r = i - plane * 264;
            int row, col;
            if (r < 136) { row = (r < 68) ? 0 : 65; col = (r < 68) ? r : r - 68; }
            else { int r2 = r - 136; row = 1 + (r2 >> 1); col = (r2 & 1) ? 65 : 0; }
            smem[plane * WPLANE + row * WSTR + col] = 0.f;
        }
        {
            const int off = (h + 1) * WSTR + (wb + 1);
            #pragma unroll
            for (int k = 0; k < 4; k++) {
                smem[off + k]              = vr[k];
                smem[WPLANE + off + k]     = vg[k];
                smem[2 * WPLANE + off + k] = vb[k];
            }
        }
        __syncthreads();
        #pragma unroll
        for (int c = 0; c < 3; c++) {
            const float* p = smem + c * WPLANE + h * WSTR + wb;  // 3x6 window TL
            float a0[6], a1[6], a2[6];
            #pragma unroll
            for (int j = 0; j < 6; j++) {
                a0[j] = p[j];
                a1[j] = p[WSTR + j];
                a2[j] = p[2 * WSTR + j];
            }
            #pragma unroll
            for (int k = 0; k < 4; k++) {
                float t0 = 0.25f * (a0[k] + a0[k + 2]) + 0.5f * a0[k + 1];
                float t1 = 0.25f * (a1[k] + a1[k + 2]) + 0.5f * a1[k + 1];
                float t2 = 0.25f * (a2[k] + a2[k + 2]) + 0.5f * a2[k + 1];
                float v = 0.25f * (t0 + t2) + 0.5f * t1;
                if (c == 0) vr[k] = v; else if (c == 1) vg[k] = v; else vb[k] = v;
            }
        }
    }

    // ================= phase 2: jitter + masks + clamp -> STG.128 ============
    const float ry = doblur ? (1.0f - 0.25f * ((h == 0) + (h == 63))) : 1.0f;
    float4 O0, O1, O2;
    float* O0p = &O0.x; float* O1p = &O1.x; float* O2p = &O2.x;
    #pragma unroll
    for (int k = 0; k < 4; k++) {
        const int wc = wb + k;
        float S = doblur ? (ry * (1.0f - 0.25f * ((wc == 0) + (wc == 63)))) : 1.0f;
        float r = vr[k], g = vg[k], bl = vb[k];
        float gray = 0.299f * r + 0.587f * g + 0.114f * bl;
        float dd = delta * S;
        float v0 = alpha * r  + beta * gray + dd;
        float v1 = alpha * g  + beta * gray + dd;
        float v2 = alpha * bl + beta * gray + dd;
        if (ehit_h && ((er_col[wc >> 5] >> (wc & 31)) & 1u)) {
            uint32_t rbase = ((uint32_t)b * 3u) * 4096u + (uint32_t)(base + k);
            v0 = u01f(rb32(kv0, kv1, rbase));
            v1 = u01f(rb32(kv0, kv1, rbase + 4096u));
            v2 = u01f(rb32(kv0, kv1, rbase + 8192u));
        }
        if (ghit_h && ((gm[wc >> 5] >> (wc & 31)) & 1u)) {
            v0 = 0.f; v1 = 0.f; v2 = 0.f;
        }
        O0p[k] = fminf(fmaxf(v0, 0.f), 1.f);
        O1p[k] = fminf(fmaxf(v1, 0.f), 1.f);
        O2p[k] = fminf(fmaxf(v2, 0.f), 1.f);
    }
    *(float4*)(o + base)            = O0;
    *(float4*)(o + HWpx + base)     = O1;
    *(float4*)(o + 2 * HWpx + base) = O2;
}

extern "C" void kernel_launch(void* const* d_in, const int* in_sizes, int n_in,
                              void* d_out, int out_size) {
    (void)in_sizes; (void)n_in; (void)out_size;
    const float* x = (const float*)d_in[0];
    float* out = (float*)d_out;
    cudaFuncSetAttribute(aug_kernel, cudaFuncAttributeMaxDynamicSharedMemorySize,
                         SMEM_BYTES);
    aug_kernel<<<BATCH, NT, SMEM_BYTES>>>(x, out);
}

// round 14
// speedup vs baseline: 1.1457x; 1.1246x over previous
#include <cuda_runtime.h>
#include <cuda_fp16.h>
#include <stdint.h>

// ============================================================================
// EnhancedAntiOverfittingAugmentation — round 14: R11 (best known) +
// compile-time Threefry key table + saturatef clamp. Nothing else touched.
//  - staging: ONE 8B entry per pixel {half2(R,G), half2(B,0)}, 68x68 entries,
//    2px zero border -> bilinear tap = 1x LDS.64 for all 3 channels
//  - column thread mapping (conflict-free gather; R13 showed quads conflict)
//  - all arithmetic fp32 (fp16 storage only; rel_err ~1.2e-4)
//  - register-resident warped image (4 px x 3 ch per thread @ NT=1024)
//  - non-blur CTAs: regs -> jitter/masks -> out; blur CTAs: fp32 SMEM overlay
// Randomness replicates JAX Threefry-2x32, threefry_partitionable=True.
// 1024 thr, 53.9KB smem, 2 CTAs/SM, 64 warps/SM.
// ============================================================================

#define NT 1024
#define BATCH 2048
#define HWpx 4096
#define CHW 12288
#define ESTRIDE 68                // entries per staging row
// blur overlay planes (1px pad), fp32, overlaid on dead staging
#define WSTR 68
#define WPLANE (66 * 68)          // 4488 floats
#define SMEM_BYTES (3 * WPLANE * 4)   // 53856 B (> staging 36992 B)

// ---------------- compile-time Threefry key table ----------------
struct TFPair { uint32_t a, b; };
constexpr uint32_t crotl(uint32_t v, int d) { return (v << d) | (v >> (32 - d)); }
constexpr TFPair ctf(uint32_t k0, uint32_t k1, uint32_t x0, uint32_t x1) {
    uint32_t ks2 = k0 ^ k1 ^ 0x1BD11BDAu;
    x0 += k0; x1 += k1;
#define CTFR(r) { x0 += x1; x1 = crotl(x1, (r)); x1 ^= x0; }
    CTFR(13) CTFR(15) CTFR(26) CTFR(6)   x0 += k1;  x1 += ks2 + 1u;
    CTFR(17) CTFR(29) CTFR(16) CTFR(24)  x0 += ks2; x1 += k0 + 2u;
    CTFR(13) CTFR(15) CTFR(26) CTFR(6)   x0 += k0;  x1 += k1 + 3u;
    CTFR(17) CTFR(29) CTFR(16) CTFR(24)  x0 += k1;  x1 += ks2 + 4u;
    CTFR(13) CTFR(15) CTFR(26) CTFR(6)   x0 += ks2; x1 += k0 + 5u;
#undef CTFR
    return {x0, x1};
}
struct KTab { uint32_t v[42]; };
constexpr KTab make_keys() {
    KTab t{};
    const int par[15] = {0,0,0,0, 2,2,2, 4,4,4,4,4,4, 5,5};
    const int chi[15] = {0,1,2,3, 0,1,2, 0,1,2,3,4,5, 0,1};
    for (int i = 0; i < 6; i++) {
        TFPair p = ctf(0u, 42u, 0u, (uint32_t)i);
        t.v[2 * i] = p.a; t.v[2 * i + 1] = p.b;
    }
    for (int i = 0; i < 15; i++) {
        int pa = par[i];
        TFPair p = ctf(t.v[2 * pa], t.v[2 * pa + 1], 0u, (uint32_t)chi[i]);
        t.v[12 + 2 * i] = p.a; t.v[13 + 2 * i] = p.b;
    }
    return t;
}
__constant__ KTab cK = make_keys();

__constant__ int   c_src[17] = {6,7,8,9,9, 1, 10,11,12, 3, 13,14,15,16, 18, 19, 20};
__constant__ int   c_cnt[17] = {0,0,0,1,2, 0, 0,0,0, 0, 0,0,0,0, 0, 0, 0};
__constant__ float c_lo[17]  = {-25.f,-15.f,0.85f,-0.15f,-0.15f, 0.f, 0.7f,0.7f,0.8f,
                                0.f, 0.02f,0.3f,0.f,0.f, 0.f, 8.f, 0.f};
__constant__ float c_hi[17]  = {25.f,15.f,1.15f,0.15f,0.15f, 1.f, 1.3f,1.3f,1.2f,
                                1.f, 0.1f,3.0f,1.f,1.f, 1.f, 32.f, 1.f};
#define DEGf 0.017453292519943295f
__constant__ float c_mul[17] = {DEGf,DEGf,1.f,1.f,1.f, 1.f, 1.f,1.f,1.f,
                                1.f, 1.f,1.f,1.f,1.f, 1.f, 1.f, 1.f};

__device__ __forceinline__ uint32_t rotl32(uint32_t v, int d) {
    return (v << d) | (v >> (32 - d));
}

// Threefry-2x32, 20 rounds (device runtime version)
__device__ __forceinline__ void tf2x32(uint32_t k0, uint32_t k1,
                                       uint32_t x0, uint32_t x1,
                                       uint32_t &o0, uint32_t &o1) {
    const uint32_t ks2 = k0 ^ k1 ^ 0x1BD11BDAu;
    x0 += k0; x1 += k1;
#define TFR(r) { x0 += x1; x1 = rotl32(x1, (r)); x1 ^= x0; }
    TFR(13) TFR(15) TFR(26) TFR(6)   x0 += k1;  x1 += ks2 + 1u;
    TFR(17) TFR(29) TFR(16) TFR(24)  x0 += ks2; x1 += k0 + 2u;
    TFR(13) TFR(15) TFR(26) TFR(6)   x0 += k0;  x1 += k1 + 3u;
    TFR(17) TFR(29) TFR(16) TFR(24)  x0 += k1;  x1 += ks2 + 4u;
    TFR(13) TFR(15) TFR(26) TFR(6)   x0 += ks2; x1 += k0 + 5u;
#undef TFR
    o0 = x0; o1 = x1;
}

__device__ __forceinline__ uint32_t rb32(uint32_t k0, uint32_t k1, uint32_t idx) {
    uint32_t a, b; tf2x32(k0, k1, 0u, idx, a, b); return a ^ b;
}

__device__ __forceinline__ float u01f(uint32_t bits) {
    return __uint_as_float((bits >> 9) | 0x3f800000u) - 1.0f;
}
__device__ __forceinline__ float unif(uint32_t bits, float lo, float hi) {
    return fmaxf(lo, u01f(bits) * (hi - lo) + lo);
}

__device__ __forceinline__ uint32_t h2u(__half2 h) {
    return *reinterpret_cast<uint32_t*>(&h);
}

struct SampleParams {
    float m00, m01, m10, m11, tx, ty;
    float br, ct, st;
    int flip, blur, eapply, gapply;
};

__global__ void __launch_bounds__(NT, 2)
aug_kernel(const float* __restrict__ gin, float* __restrict__ gout) {
    extern __shared__ float smem[];
    uint2* sPix = (uint2*)smem;    // staging: {h2(R,G), h2(B,0)} per px
    __shared__ SampleParams P;
    __shared__ float red[NT / 32];
    __shared__ float U[17];
    __shared__ uint32_t gm[2], er_row[2], er_col[2];

    const int b = blockIdx.x;
    const int tid = threadIdx.x;

    // ================= params (warp 0): 17 uniforms from constexpr keys ======
    if (tid < 32) {
        const int lane = tid;
        const uint32_t ub = (uint32_t)b;
        {
            int li = min(lane, 16);
            int s = c_src[li];
            int cs = c_cnt[li];
            uint32_t cnt = (cs == 0) ? ub : ((cs == 1) ? 2u * ub : 2u * ub + 1u);
            uint32_t bits = rb32(cK.v[2 * s], cK.v[2 * s + 1], cnt);
            float u = unif(bits, c_lo[li], c_hi[li]) * c_mul[li];
            if (lane == 15) u = floorf(u);
            if (lane < 17) U[lane] = u;
        }
        __syncwarp();
        {
            float ang = U[0], shr = U[1], scl = U[2];
            float cc = cosf(ang), ss = sinf(ang), t = tanf(shr);
            float m00 = (cc - t * (-ss)) / scl;
            float m01 = (ss - t * cc) / scl;
            float m10 = (-ss) / scl;
            float m11 = cc / scl;
            float area = (U[10] * 64.0f) * 64.0f;
            float ratio = U[11];
            float eh = fminf(fmaxf(sqrtf(area * ratio), 1.0f), 64.0f);
            float ew = fminf(fmaxf(sqrtf(area / ratio), 1.0f), 64.0f);
            float top = U[12] * (64.0f - eh);
            float left = U[13] * (64.0f - ew);
            if (lane == 0) {
                P.m00 = m00; P.m01 = m01; P.m10 = m10; P.m11 = m11;
                P.tx = U[3] * 64.0f;  P.ty = U[4] * 64.0f;
                P.flip = (U[5] < 0.6f);
                P.br = U[6]; P.ct = U[7]; P.st = U[8];
                P.blur = (U[9] < 0.3f);
                P.eapply = (U[14] < 0.3f);
                P.gapply = (U[16] < 0.3f);
            }
            __syncwarp();
            float c0 = (float)lane, c1 = (float)(lane + 32);
            float gd = U[15], gl = floorf(U[15] * 0.6f);
            uint32_t g0 = __ballot_sync(0xffffffffu, fmodf(c0, gd) < gl);
            uint32_t g1 = __ballot_sync(0xffffffffu, fmodf(c1, gd) < gl);
            uint32_t r0 = __ballot_sync(0xffffffffu, c0 >= top && c0 < top + eh);
            uint32_t r1 = __ballot_sync(0xffffffffu, c1 >= top && c1 < top + eh);
            uint32_t q0 = __ballot_sync(0xffffffffu, c0 >= left && c0 < left + ew);
            uint32_t q1 = __ballot_sync(0xffffffffu, c1 >= left && c1 < left + ew);
            if (lane == 0) {
                gm[0] = g0; gm[1] = g1;
                er_row[0] = r0; er_row[1] = r1;
                er_col[0] = q0; er_col[1] = q1;
            }
        }
    }

    // ================= staging border zero (264 uint4 = 16B each) ============
    if (tid < 264) {
        int i = tid;
        int eidx;                       // entry index (8B units), even
        if (i < 136) {
            int r = i / 34, c2 = i % 34;
            int row = (r < 2) ? r : 64 + r;
            eidx = row * ESTRIDE + c2 * 2;
        } else {
            int j = i - 136;
            int r = 2 + (j >> 1);
            eidx = r * ESTRIDE + ((j & 1) ? 66 : 0);
        }
        *(uint4*)(sPix + eidx) = make_uint4(0u, 0u, 0u, 0u);
    }

    // ================= interior load: planar global -> packed entries ========
    {
        const float4* gin4 = (const float4*)(gin + (size_t)b * CHW);
        int q = tid;                           // one quad (4px) per thread
        float4 R4 = gin4[q];
        float4 G4 = gin4[q + 1024];
        float4 B4 = gin4[q + 2048];
        int h = q >> 4, w = (q & 15) << 2;
        int ebase = (h + 2) * ESTRIDE + (w + 2);   // even -> 16B aligned
        uint4 u0 = make_uint4(
            h2u(__floats2half2_rn(R4.x, G4.x)), h2u(__floats2half2_rn(B4.x, 0.f)),
            h2u(__floats2half2_rn(R4.y, G4.y)), h2u(__floats2half2_rn(B4.y, 0.f)));
        uint4 u1 = make_uint4(
            h2u(__floats2half2_rn(R4.z, G4.z)), h2u(__floats2half2_rn(B4.z, 0.f)),
            h2u(__floats2half2_rn(R4.w, G4.w)), h2u(__floats2half2_rn(B4.w, 0.f)));
        *(uint4*)(sPix + ebase)     = u0;
        *(uint4*)(sPix + ebase + 2) = u1;
    }
    __syncthreads();

    // ================= phase 1: gather into registers + sum ==================
    const float m00 = P.m00, m01 = P.m01, m10 = P.m10, m11 = P.m11;
    const bool flip = P.flip;
    const bool doblur = P.blur;
    const int w = tid & 63;
    const int h0 = tid >> 6;         // 0..15; rows h0 + 16k
    const int wd = flip ? (63 - w) : w;

    float vr[4], vg[4], vb[4];
    {
        const float gx = (float)w - 31.5f;
        float sx = m00 * gx + m01 * ((float)h0 - 31.5f) - P.tx + 31.5f;
        float sy = m10 * gx + m11 * ((float)h0 - 31.5f) - P.ty + 31.5f;
        const float dx16 = 16.0f * m01, dy16 = 16.0f * m11;
        float lsum = 0.f;
        #pragma unroll
        for (int k = 0; k < 4; k++) {
            float x0f = floorf(sx), y0f = floorf(sy);
            float wx = sx - x0f, wy = sy - y0f;
            int xi = min(max((int)x0f, -2), 64);
            int yi = min(max((int)y0f, -2), 64);
            const int eidx = (yi + 2) * ESTRIDE + (xi + 2);
            uint2 e00 = sPix[eidx];
            uint2 e01 = sPix[eidx + 1];
            uint2 e10 = sPix[eidx + ESTRIDE];
            uint2 e11 = sPix[eidx + ESTRIDE + 1];
            float2 p00 = __half22float2(*(const __half2*)&e00.x);
            float2 p01 = __half22float2(*(const __half2*)&e01.x);
            float2 p10 = __half22float2(*(const __half2*)&e10.x);
            float2 p11 = __half22float2(*(const __half2*)&e11.x);
            float b00 = __half2float(*(const __half*)&e00.y);
            float b01 = __half2float(*(const __half*)&e01.y);
            float b10 = __half2float(*(const __half*)&e10.y);
            float b11 = __half2float(*(const __half*)&e11.y);
            float w11 = wx * wy;
            float w01 = wx - w11;
            float w10 = wy - w11;
            float w00 = 1.0f - wx - wy + w11;
            vr[k] = p00.x * w00 + p01.x * w01 + p10.x * w10 + p11.x * w11;
            vg[k] = p00.y * w00 + p01.y * w01 + p10.y * w10 + p11.y * w11;
            vb[k] = b00  * w00 + b01  * w01 + b10  * w10 + b11  * w11;
            lsum += vr[k] + vg[k] + vb[k];
            sx += dx16; sy += dy16;
        }
        #pragma unroll
        for (int off = 16; off > 0; off >>= 1)
            lsum += __shfl_xor_sync(0xffffffffu, lsum, off);
        if ((tid & 31) == 0) red[tid >> 5] = lsum;
    }
    __syncthreads();   // red ready; staging now DEAD (all gathers done)

    // ---------------- per-warp mean finish (32 partials) ----------------
    float alpha, beta, delta;
    {
        const int lane = tid & 31;
        float t = red[lane];
        #pragma unroll
        for (int off = 16; off > 0; off >>= 1)
            t += __shfl_xor_sync(0xffffffffu, t, off);
        float mean = (P.br * t) * (1.0f / 12288.0f);
        float bc = P.br * P.ct;
        alpha = P.st * bc;
        beta  = (1.0f - P.st) * bc;
        delta = mean * (1.0f - P.ct);
    }
    const bool eap = P.eapply, gap = P.gapply;
    const uint32_t kv0 = cK.v[34], kv1 = cK.v[35];
    float* o = gout + (size_t)b * CHW;
    const bool ecol_hit = eap && ((er_col[wd >> 5] >> (wd & 31)) & 1u);
    const bool gcol_hit = gap && ((gm[wd >> 5] >> (wd & 31)) & 1u);

    if (!doblur) {
        // ========== non-blur: jitter + masks + clamp straight from regs ======
        #pragma unroll
        for (int k = 0; k < 4; k++) {
            const int h = h0 + 16 * k;
            float r = vr[k], g = vg[k], bl = vb[k];
            float gray = 0.299f * r + 0.587f * g + 0.114f * bl;
            float v0 = alpha * r  + beta * gray + delta;
            float v1 = alpha * g  + beta * gray + delta;
            float v2 = alpha * bl + beta * gray + delta;
            if (ecol_hit && ((er_row[h >> 5] >> (h & 31)) & 1u)) {
                uint32_t rbase = ((uint32_t)b * 3u) * 4096u + (uint32_t)(h * 64 + wd);
                v0 = u01f(rb32(kv0, kv1, rbase));
                v1 = u01f(rb32(kv0, kv1, rbase + 4096u));
                v2 = u01f(rb32(kv0, kv1, rbase + 8192u));
            }
            if (gcol_hit && ((gm[h >> 5] >> (h & 31)) & 1u)) {
                v0 = 0.f; v1 = 0.f; v2 = 0.f;
            }
            const int base = h * 64 + wd;
            o[base]            = __saturatef(v0);
            o[HWpx + base]     = __saturatef(v1);
            o[2 * HWpx + base] = __saturatef(v2);
        }
    } else {
        // ========== blur: spill regs -> fp32 padded overlay, 9-tap, jitter ===
        if (tid < 792) {
            int i = tid;
            int plane = i / 264;
            int r = i - plane * 264;
            int row, col;
            if (r < 136) { row = (r < 68) ? 0 : 65; col = (r < 68) ? r : r - 68; }
            else { int r2 = r - 136; row = 1 + (r2 >> 1); col = (r2 & 1) ? 65 : 0; }
            smem[plane * WPLANE + row * WSTR + col] = 0.f;
        }
        #pragma unroll
        for (int k = 0; k < 4; k++) {
            const int h = h0 + 16 * k;
            const int off = (h + 1) * WSTR + (wd + 1);
            smem[off]              = vr[k];
            smem[WPLANE + off]     = vg[k];
            smem[2 * WPLANE + off] = vb[k];
        }
        __syncthreads();

        const float rx = 1.0f - 0.25f * ((wd == 0) + (wd == 63));
        #pragma unroll
        for (int k = 0; k < 4; k++) {
            const int h = h0 + 16 * k;
            float v[3];
            #pragma unroll
            for (int c = 0; c < 3; c++) {
                const float* p = smem + c * WPLANE + h * WSTR + wd;  // window TL
                float t0 = 0.25f * (p[0] + p[2]) + 0.5f * p[1];
                float t1 = 0.25f * (p[WSTR] + p[WSTR + 2]) + 0.5f * p[WSTR + 1];
                float t2 = 0.25f * (p[2 * WSTR] + p[2 * WSTR + 2]) + 0.5f * p[2 * WSTR + 1];
                v[c] = 0.25f * (t0 + t2) + 0.5f * t1;
            }
            float S = rx * (1.0f - 0.25f * ((h == 0) + (h == 63)));
            float gray = 0.299f * v[0] + 0.587f * v[1] + 0.114f * v[2];
            float dd = delta * S;
            float v0 = alpha * v[0] + beta * gray + dd;
            float v1 = alpha * v[1] + beta * gray + dd;
            float v2 = alpha * v[2] + beta * gray + dd;
            if (ecol_hit && ((er_row[h >> 5] >> (h & 31)) & 1u)) {
                uint32_t rbase = ((uint32_t)b * 3u) * 4096u + (uint32_t)(h * 64 + wd);
                v0 = u01f(rb32(kv0, kv1, rbase));
                v1 = u01f(rb32(kv0, kv1, rbase + 4096u));
                v2 = u01f(rb32(kv0, kv1, rbase + 8192u));
            }
            if (gcol_hit && ((gm[h >> 5] >> (h & 31)) & 1u)) {
                v0 = 0.f; v1 = 0.f; v2 = 0.f;
            }
            const int base = h * 64 + wd;
            o[base]            = __saturatef(v0);
            o[HWpx + base]     = __saturatef(v1);
            o[2 * HWpx + base] = __saturatef(v2);
        }
    }
}

extern "C" void kernel_launch(void* const* d_in, const int* in_sizes, int n_in,
                              void* d_out, int out_size) {
    (void)in_sizes; (void)n_in; (void)out_size;
    const float* x = (const float*)d_in[0];
    float* out = (float*)d_out;
    cudaFuncSetAttribute(aug_kernel, cudaFuncAttributeMaxDynamicSharedMemorySize,
                         SMEM_BYTES);
    aug_kernel<<<BATCH, NT, SMEM_BYTES>>>(x, out);
}